// round 1
// baseline (speedup 1.0000x reference)
#include <cuda_runtime.h>
#include <math.h>

#define N_TOK 4096
#define D_IN  512
#define E_EXP 8
#define TOPK  2
#define H_DIM 2048

#define TM 64
#define TN 64
#define TK 16
#define SLOTS (N_TOK*TOPK + E_EXP*TM)   // 8192 + 512 = 8704 padded slots

// -------- scratch (device globals; no allocation allowed) --------
__device__ int   g_counts[E_EXP];
__device__ int   g_off[E_EXP + 1];
__device__ int   g_wptr[E_EXP];
__device__ int   g_slot_tok[SLOTS];
__device__ float g_slot_w[SLOTS];
__device__ int   g_tok_slot[N_TOK * TOPK];   // (token,k) -> slot
__device__ float g_topw[N_TOK * TOPK];
__device__ int   g_topi[N_TOK * TOPK];
__device__ float g_hidden[(size_t)SLOTS * H_DIM]; // 71.3 MB
__device__ float g_ybuf[(size_t)SLOTS * D_IN];    // 17.8 MB

// -------- init --------
__global__ void init_kernel() {
    int i = blockIdx.x * blockDim.x + threadIdx.x;
    if (i < E_EXP) g_counts[i] = 0;
    if (i < SLOTS) g_slot_tok[i] = -1;
}

// -------- gating: one warp per token --------
__global__ void gate_kernel(const float* __restrict__ x,
                            const float* __restrict__ Wg,
                            const float* __restrict__ bg,
                            float* __restrict__ gates_out) {
    int t    = (blockIdx.x * blockDim.x + threadIdx.x) >> 5;
    int lane = threadIdx.x & 31;
    if (t >= N_TOK) return;
    const float* xr = x + (size_t)t * D_IN;

    float acc[E_EXP];
#pragma unroll
    for (int e = 0; e < E_EXP; e++) acc[e] = 0.f;

    for (int d = lane; d < D_IN; d += 32) {
        float xv = xr[d];
        const float* wr = Wg + d * E_EXP;
#pragma unroll
        for (int e = 0; e < E_EXP; e++) acc[e] = fmaf(xv, wr[e], acc[e]);
    }
#pragma unroll
    for (int o = 16; o > 0; o >>= 1) {
#pragma unroll
        for (int e = 0; e < E_EXP; e++)
            acc[e] += __shfl_xor_sync(0xffffffffu, acc[e], o);
    }
    if (lane == 0) {
        float l[E_EXP], p[E_EXP];
        float m = -1e30f;
#pragma unroll
        for (int e = 0; e < E_EXP; e++) { l[e] = acc[e] + bg[e]; m = fmaxf(m, l[e]); }
        float s = 0.f;
#pragma unroll
        for (int e = 0; e < E_EXP; e++) { p[e] = __expf(l[e] - m); s += p[e]; }
        float inv = 1.f / s;
#pragma unroll
        for (int e = 0; e < E_EXP; e++) p[e] *= inv;

        if (gates_out) {
#pragma unroll
            for (int e = 0; e < E_EXP; e++) gates_out[t * E_EXP + e] = p[e];
        }
        // top-2 (strict > keeps lowest index on ties, matching jax top_k)
        int i1 = 0; float p1 = p[0];
#pragma unroll
        for (int e = 1; e < E_EXP; e++) if (p[e] > p1) { p1 = p[e]; i1 = e; }
        int i2 = -1; float p2 = -1.f;
#pragma unroll
        for (int e = 0; e < E_EXP; e++) if (e != i1 && p[e] > p2) { p2 = p[e]; i2 = e; }

        g_topw[t * 2 + 0] = p1;  g_topi[t * 2 + 0] = i1;
        g_topw[t * 2 + 1] = p2;  g_topi[t * 2 + 1] = i2;
        atomicAdd(&g_counts[i1], 1);
        atomicAdd(&g_counts[i2], 1);
    }
}

// -------- tiny scan: padded segment offsets --------
__global__ void scan_kernel() {
    if (threadIdx.x == 0 && blockIdx.x == 0) {
        int o = 0;
        for (int e = 0; e < E_EXP; e++) {
            g_off[e]  = o;
            g_wptr[e] = o;
            o += ((g_counts[e] + TM - 1) / TM) * TM;
        }
        g_off[E_EXP] = o;
    }
}

// -------- scatter tokens into expert segments --------
__global__ void scatter_kernel() {
    int i = blockIdx.x * blockDim.x + threadIdx.x;
    if (i >= N_TOK * TOPK) return;
    int e = g_topi[i];
    int pos = atomicAdd(&g_wptr[e], 1);
    g_slot_tok[pos] = i >> 1;
    g_slot_w[pos]   = g_topw[i];
    g_tok_slot[i]   = pos;
}

// -------- grouped SGEMM1: hidden = relu(x[slots] @ W1[e] + b1[e]) --------
__global__ void __launch_bounds__(256)
gemm1_kernel(const float* __restrict__ x,
             const float* __restrict__ W1,
             const float* __restrict__ b1) {
    __shared__ __align__(16) float As[TK][TM];
    __shared__ __align__(16) float Bs[TK][TN];
    __shared__ int sTok[TM];

    int m0 = blockIdx.y * TM;
    int n0 = blockIdx.x * TN;
    if (m0 >= g_off[E_EXP]) return;
    int e = 0;
#pragma unroll
    for (int i = 1; i < E_EXP; i++) if (m0 >= g_off[i]) e = i;

    int tid = threadIdx.x;
    if (tid < TM) sTok[tid] = g_slot_tok[m0 + tid];
    __syncthreads();

    const float* B = W1 + (size_t)e * D_IN * H_DIM;

    int am = tid >> 2, ak = (tid & 3) << 2;          // A loader: 64x16 via float4
    int bk = tid >> 4, bn = (tid & 15) << 2;         // B loader: 16x64 via float4
    int tx = tid & 15, ty = tid >> 4;

    int tokA = sTok[am];
    const float* aptr = (tokA >= 0) ? (x + (size_t)tokA * D_IN + ak) : nullptr;

    float acc[4][4];
#pragma unroll
    for (int i = 0; i < 4; i++)
#pragma unroll
        for (int j = 0; j < 4; j++) acc[i][j] = 0.f;

    for (int k0 = 0; k0 < D_IN; k0 += TK) {
        float4 av = aptr ? *(const float4*)(aptr + k0) : make_float4(0.f, 0.f, 0.f, 0.f);
        As[ak + 0][am] = av.x; As[ak + 1][am] = av.y;
        As[ak + 2][am] = av.z; As[ak + 3][am] = av.w;

        float4 bv = *(const float4*)(B + (size_t)(k0 + bk) * H_DIM + n0 + bn);
        *(float4*)&Bs[bk][bn] = bv;
        __syncthreads();
#pragma unroll
        for (int k = 0; k < TK; k++) {
            float4 a = *(const float4*)&As[k][ty << 2];
            float4 b = *(const float4*)&Bs[k][tx << 2];
            float ar[4] = {a.x, a.y, a.z, a.w};
            float br[4] = {b.x, b.y, b.z, b.w};
#pragma unroll
            for (int i = 0; i < 4; i++)
#pragma unroll
                for (int j = 0; j < 4; j++)
                    acc[i][j] = fmaf(ar[i], br[j], acc[i][j]);
        }
        __syncthreads();
    }

    const float* bias = b1 + (size_t)e * H_DIM;
#pragma unroll
    for (int i = 0; i < 4; i++) {
        int m = m0 + (ty << 2) + i;
        float* hrow = g_hidden + (size_t)m * H_DIM + n0 + (tx << 2);
        float4 v;
        v.x = fmaxf(acc[i][0] + bias[n0 + (tx << 2) + 0], 0.f);
        v.y = fmaxf(acc[i][1] + bias[n0 + (tx << 2) + 1], 0.f);
        v.z = fmaxf(acc[i][2] + bias[n0 + (tx << 2) + 2], 0.f);
        v.w = fmaxf(acc[i][3] + bias[n0 + (tx << 2) + 3], 0.f);
        *(float4*)hrow = v;
    }
}

// -------- grouped SGEMM2: y[slot] = (hidden @ W2[e] + b2[e]) * w[slot] --------
__global__ void __launch_bounds__(256)
gemm2_kernel(const float* __restrict__ W2,
             const float* __restrict__ b2) {
    __shared__ __align__(16) float As[TK][TM];
    __shared__ __align__(16) float Bs[TK][TN];
    __shared__ float sW[TM];

    int m0 = blockIdx.y * TM;
    int n0 = blockIdx.x * TN;
    if (m0 >= g_off[E_EXP]) return;
    int e = 0;
#pragma unroll
    for (int i = 1; i < E_EXP; i++) if (m0 >= g_off[i]) e = i;

    int tid = threadIdx.x;
    if (tid < TM) sW[tid] = g_slot_w[m0 + tid];
    __syncthreads();

    const float* B = W2 + (size_t)e * H_DIM * D_IN;

    int am = tid >> 2, ak = (tid & 3) << 2;
    int bk = tid >> 4, bn = (tid & 15) << 2;
    int tx = tid & 15, ty = tid >> 4;

    const float* aptr = g_hidden + (size_t)(m0 + am) * H_DIM + ak;

    float acc[4][4];
#pragma unroll
    for (int i = 0; i < 4; i++)
#pragma unroll
        for (int j = 0; j < 4; j++) acc[i][j] = 0.f;

    for (int k0 = 0; k0 < H_DIM; k0 += TK) {
        float4 av = *(const float4*)(aptr + k0);
        As[ak + 0][am] = av.x; As[ak + 1][am] = av.y;
        As[ak + 2][am] = av.z; As[ak + 3][am] = av.w;

        float4 bv = *(const float4*)(B + (size_t)(k0 + bk) * D_IN + n0 + bn);
        *(float4*)&Bs[bk][bn] = bv;
        __syncthreads();
#pragma unroll
        for (int k = 0; k < TK; k++) {
            float4 a = *(const float4*)&As[k][ty << 2];
            float4 b = *(const float4*)&Bs[k][tx << 2];
            float ar[4] = {a.x, a.y, a.z, a.w};
            float br[4] = {b.x, b.y, b.z, b.w};
#pragma unroll
            for (int i = 0; i < 4; i++)
#pragma unroll
                for (int j = 0; j < 4; j++)
                    acc[i][j] = fmaf(ar[i], br[j], acc[i][j]);
        }
        __syncthreads();
    }

    const float* bias = b2 + (size_t)e * D_IN;
#pragma unroll
    for (int i = 0; i < 4; i++) {
        int m = m0 + (ty << 2) + i;
        float w = sW[(ty << 2) + i];
        float* yrow = g_ybuf + (size_t)m * D_IN + n0 + (tx << 2);
        float4 v;
        v.x = (acc[i][0] + bias[n0 + (tx << 2) + 0]) * w;
        v.y = (acc[i][1] + bias[n0 + (tx << 2) + 1]) * w;
        v.z = (acc[i][2] + bias[n0 + (tx << 2) + 2]) * w;
        v.w = (acc[i][3] + bias[n0 + (tx << 2) + 3]) * w;
        *(float4*)yrow = v;
    }
}

// -------- deterministic combine: out[t] = y[slot(t,0)] + y[slot(t,1)] --------
__global__ void combine_kernel(float* __restrict__ out) {
    int i = blockIdx.x * blockDim.x + threadIdx.x;   // one float4 per thread
    if (i >= N_TOK * (D_IN / 4)) return;
    int t  = i >> 7;            // D_IN/4 = 128
    int dd = (i & 127) << 2;
    int s0 = g_tok_slot[t * 2 + 0];
    int s1 = g_tok_slot[t * 2 + 1];
    float4 a = *(const float4*)(g_ybuf + (size_t)s0 * D_IN + dd);
    float4 b = *(const float4*)(g_ybuf + (size_t)s1 * D_IN + dd);
    float4 r = make_float4(a.x + b.x, a.y + b.y, a.z + b.z, a.w + b.w);
    *(float4*)(out + (size_t)t * D_IN + dd) = r;
}

extern "C" void kernel_launch(void* const* d_in, const int* in_sizes, int n_in,
                              void* d_out, int out_size) {
    const float* x  = (const float*)d_in[0];
    const float* Wg = (const float*)d_in[1];
    const float* bg = (const float*)d_in[2];
    const float* W1 = (const float*)d_in[3];
    const float* b1 = (const float*)d_in[4];
    const float* W2 = (const float*)d_in[5];
    const float* b2 = (const float*)d_in[6];
    float* out = (float*)d_out;

    float* gates_out = nullptr;
    if (out_size >= N_TOK * D_IN + N_TOK * E_EXP)
        gates_out = out + (size_t)N_TOK * D_IN;

    init_kernel<<<(SLOTS + 255) / 256, 256>>>();
    gate_kernel<<<(N_TOK * 32 + 255) / 256, 256>>>(x, Wg, bg, gates_out);
    scan_kernel<<<1, 32>>>();
    scatter_kernel<<<(N_TOK * TOPK + 255) / 256, 256>>>();

    dim3 g1(H_DIM / TN, SLOTS / TM);   // (32, 136)
    gemm1_kernel<<<g1, 256>>>(x, W1, b1);

    dim3 g2(D_IN / TN, SLOTS / TM);    // (8, 136)
    gemm2_kernel<<<g2, 256>>>(W2, b2);

    combine_kernel<<<(N_TOK * (D_IN / 4) + 255) / 256, 256>>>(out);
}

// round 4
// speedup vs baseline: 2.0978x; 2.0978x over previous
#include <cuda_runtime.h>
#include <cuda_bf16.h>
#include <math.h>
#include <stdint.h>

#define N_TOK 4096
#define D_IN  512
#define E_EXP 8
#define TOPK  2
#define H_DIM 2048

#define BM 128
#define BN 128
#define BK 32
#define SLOTS (N_TOK*TOPK + E_EXP*BM)   // 9216 padded slots

// smem plane: 128 rows x 32 bf16, row stride 40 bf16 = 20 u32 (conflict-free)
#define ROW_U32 20
#define PLANE_U32 (128 * ROW_U32)            // 2560
#define STAGE_U32 (4 * PLANE_U32)            // Ah,Al,Bh,Bl = 10240
#define SMEM_BYTES (2 * STAGE_U32 * 4)       // 81920

// -------- scratch (device globals; no allocation allowed) --------
__device__ int   g_counts[E_EXP];
__device__ int   g_off[E_EXP + 1];
__device__ int   g_wptr[E_EXP];
__device__ int   g_slot_tok[SLOTS];
__device__ float g_slot_w[SLOTS];
__device__ int   g_tok_slot[N_TOK * TOPK];
__device__ float g_topw[N_TOK * TOPK];
__device__ int   g_topi[N_TOK * TOPK];

__device__ __nv_bfloat16 gx_hi[(size_t)N_TOK * D_IN];
__device__ __nv_bfloat16 gx_lo[(size_t)N_TOK * D_IN];
__device__ __nv_bfloat16 gW1t_hi[(size_t)E_EXP * H_DIM * D_IN]; // [e][n][k]
__device__ __nv_bfloat16 gW1t_lo[(size_t)E_EXP * H_DIM * D_IN];
__device__ __nv_bfloat16 gW2t_hi[(size_t)E_EXP * D_IN * H_DIM]; // [e][n][k]
__device__ __nv_bfloat16 gW2t_lo[(size_t)E_EXP * D_IN * H_DIM];
__device__ __nv_bfloat16 gh_hi[(size_t)SLOTS * H_DIM];
__device__ __nv_bfloat16 gh_lo[(size_t)SLOTS * H_DIM];
__device__ float g_ybuf[(size_t)SLOTS * D_IN];

// -------- async-copy helpers --------
__device__ __forceinline__ void cp16(uint32_t dst, const void* src, int srcBytes) {
    asm volatile("cp.async.cg.shared.global [%0], [%1], 16, %2;"
                 :: "r"(dst), "l"(src), "r"(srcBytes) : "memory");
}
__device__ __forceinline__ void cp_commit() {
    asm volatile("cp.async.commit_group;" ::: "memory");
}
template<int N> __device__ __forceinline__ void cp_wait() {
    asm volatile("cp.async.wait_group %0;" :: "n"(N) : "memory");
}

__device__ __forceinline__ void mma_bf16(float d[4],
                                         uint32_t a0, uint32_t a1, uint32_t a2, uint32_t a3,
                                         uint32_t b0, uint32_t b1) {
    asm volatile(
        "mma.sync.aligned.m16n8k16.row.col.f32.bf16.bf16.f32 "
        "{%0,%1,%2,%3},{%4,%5,%6,%7},{%8,%9},{%0,%1,%2,%3};"
        : "+f"(d[0]), "+f"(d[1]), "+f"(d[2]), "+f"(d[3])
        : "r"(a0), "r"(a1), "r"(a2), "r"(a3), "r"(b0), "r"(b1));
}

// -------- init --------
__global__ void init_kernel() {
    int i = blockIdx.x * blockDim.x + threadIdx.x;
    if (i < E_EXP) g_counts[i] = 0;
    if (i < SLOTS) g_slot_tok[i] = -1;
}

// -------- gating: one warp per token --------
__global__ void gate_kernel(const float* __restrict__ x,
                            const float* __restrict__ Wg,
                            const float* __restrict__ bg,
                            float* __restrict__ gates_out) {
    int t    = (blockIdx.x * blockDim.x + threadIdx.x) >> 5;
    int lane = threadIdx.x & 31;
    if (t >= N_TOK) return;
    const float* xr = x + (size_t)t * D_IN;

    float acc[E_EXP];
#pragma unroll
    for (int e = 0; e < E_EXP; e++) acc[e] = 0.f;

    for (int d = lane; d < D_IN; d += 32) {
        float xv = xr[d];
        const float* wr = Wg + d * E_EXP;
#pragma unroll
        for (int e = 0; e < E_EXP; e++) acc[e] = fmaf(xv, wr[e], acc[e]);
    }
#pragma unroll
    for (int o = 16; o > 0; o >>= 1) {
#pragma unroll
        for (int e = 0; e < E_EXP; e++)
            acc[e] += __shfl_xor_sync(0xffffffffu, acc[e], o);
    }
    if (lane == 0) {
        float l[E_EXP], p[E_EXP];
        float m = -1e30f;
#pragma unroll
        for (int e = 0; e < E_EXP; e++) { l[e] = acc[e] + bg[e]; m = fmaxf(m, l[e]); }
        float s = 0.f;
#pragma unroll
        for (int e = 0; e < E_EXP; e++) { p[e] = __expf(l[e] - m); s += p[e]; }
        float inv = 1.f / s;
#pragma unroll
        for (int e = 0; e < E_EXP; e++) p[e] *= inv;

        if (gates_out) {
#pragma unroll
            for (int e = 0; e < E_EXP; e++) gates_out[t * E_EXP + e] = p[e];
        }
        int i1 = 0; float p1 = p[0];
#pragma unroll
        for (int e = 1; e < E_EXP; e++) if (p[e] > p1) { p1 = p[e]; i1 = e; }
        int i2 = -1; float p2 = -1.f;
#pragma unroll
        for (int e = 0; e < E_EXP; e++) if (e != i1 && p[e] > p2) { p2 = p[e]; i2 = e; }

        g_topw[t * 2 + 0] = p1;  g_topi[t * 2 + 0] = i1;
        g_topw[t * 2 + 1] = p2;  g_topi[t * 2 + 1] = i2;
        atomicAdd(&g_counts[i1], 1);
        atomicAdd(&g_counts[i2], 1);
    }
}

// -------- tiny scan --------
__global__ void scan_kernel() {
    if (threadIdx.x == 0 && blockIdx.x == 0) {
        int o = 0;
        for (int e = 0; e < E_EXP; e++) {
            g_off[e]  = o;
            g_wptr[e] = o;
            o += ((g_counts[e] + BM - 1) / BM) * BM;
        }
        g_off[E_EXP] = o;
    }
}

// -------- scatter --------
__global__ void scatter_kernel() {
    int i = blockIdx.x * blockDim.x + threadIdx.x;
    if (i >= N_TOK * TOPK) return;
    int e = g_topi[i];
    int pos = atomicAdd(&g_wptr[e], 1);
    g_slot_tok[pos] = i >> 1;
    g_slot_w[pos]   = g_topw[i];
    g_tok_slot[i]   = pos;
}

// -------- fp32 -> bf16 hi/lo split, elementwise (for x) --------
__global__ void split_x_kernel(const float* __restrict__ src) {
    int i = blockIdx.x * blockDim.x + threadIdx.x;
    if (i >= N_TOK * D_IN) return;
    float v = src[i];
    __nv_bfloat16 h = __float2bfloat16(v);
    gx_hi[i] = h;
    gx_lo[i] = __float2bfloat16(v - __bfloat162float(h));
}

// -------- fp32 [E][K][N] -> transposed bf16 hi/lo planes [E][N][K] --------
__global__ void split_wt_kernel(const float* __restrict__ src,
                                __nv_bfloat16* __restrict__ dhi,
                                __nv_bfloat16* __restrict__ dlo,
                                int K, int N) {
    __shared__ float t[32][33];
    int e = blockIdx.z;
    int k0 = blockIdx.y * 32, n0 = blockIdx.x * 32;
    const float* s = src + (size_t)e * K * N;
    int tx = threadIdx.x & 31, ty = threadIdx.x >> 5;
#pragma unroll
    for (int i = 0; i < 4; i++)
        t[ty + 8 * i][tx] = s[(size_t)(k0 + ty + 8 * i) * N + n0 + tx];
    __syncthreads();
    size_t ob = (size_t)e * K * N;
#pragma unroll
    for (int i = 0; i < 4; i++) {
        int n = n0 + ty + 8 * i, k = k0 + tx;
        float v = t[tx][ty + 8 * i];
        __nv_bfloat16 h = __float2bfloat16(v);
        dhi[ob + (size_t)n * K + k] = h;
        dlo[ob + (size_t)n * K + k] = __float2bfloat16(v - __bfloat162float(h));
    }
}

// -------- grouped bf16x3 tensor-core GEMM --------
// A planes: [rows][KTOT] bf16 hi/lo (gathered by slot for gemm1).
// B planes: [E][NTOT][KTOT] bf16 hi/lo (transposed weights).
template<int KTOT, int NTOT, bool GATHER, bool RELU, bool SCALE>
__global__ void __launch_bounds__(256, 2)
mma_gemm_kernel(const __nv_bfloat16* __restrict__ Ahi,
                const __nv_bfloat16* __restrict__ Alo,
                const __nv_bfloat16* __restrict__ Bthi,
                const __nv_bfloat16* __restrict__ Btlo,
                const float* __restrict__ Bias)
{
    constexpr int KT = KTOT / BK;
    extern __shared__ uint32_t sm[];
    __shared__ int   sTok[BM];
    __shared__ float sW[BM];

    const int m0 = blockIdx.y * BM;
    const int n0 = blockIdx.x * BN;
    if (m0 >= g_off[E_EXP]) return;
    int e = 0;
#pragma unroll
    for (int i = 1; i < E_EXP; i++) if (m0 >= g_off[i]) e = i;

    const int tid = threadIdx.x;
    if (tid < BM) {
        if (GATHER) sTok[tid] = g_slot_tok[m0 + tid];
        if (SCALE)  sW[tid]   = g_slot_w[m0 + tid];
    }
    __syncthreads();

    const __nv_bfloat16* Wh = Bthi + (size_t)e * NTOT * KTOT;
    const __nv_bfloat16* Wl = Btlo + (size_t)e * NTOT * KTOT;

    // staging: thread -> row tid>>1, k-halfchunk (tid&1)*16 bf16
    const int srow = tid >> 1;
    const int skoff = (tid & 1) * 16;

    const __nv_bfloat16 *arow_h, *arow_l;
    int abytes = 16;
    if (GATHER) {
        int tok = sTok[srow];
        if (tok >= 0) {
            arow_h = Ahi + (size_t)tok * KTOT + skoff;
            arow_l = Alo + (size_t)tok * KTOT + skoff;
        } else { arow_h = Ahi; arow_l = Alo; abytes = 0; }
    } else {
        arow_h = Ahi + (size_t)(m0 + srow) * KTOT + skoff;
        arow_l = Alo + (size_t)(m0 + srow) * KTOT + skoff;
    }
    const __nv_bfloat16* brow_h = Wh + (size_t)(n0 + srow) * KTOT + skoff;
    const __nv_bfloat16* brow_l = Wl + (size_t)(n0 + srow) * KTOT + skoff;

    // smem byte addresses for this thread's staging target
    const uint32_t smem_base = (uint32_t)__cvta_generic_to_shared(sm);
    const uint32_t trg = smem_base + (srow * ROW_U32 + (skoff >> 1)) * 4;

    auto stage = [&](int s, int k0k) {
        uint32_t sb = trg + s * (STAGE_U32 * 4);
        cp16(sb + 0 * PLANE_U32 * 4,      arow_h + k0k, abytes);
        cp16(sb + 0 * PLANE_U32 * 4 + 16, arow_h + k0k + 8, abytes);
        cp16(sb + 1 * PLANE_U32 * 4,      arow_l + k0k, abytes);
        cp16(sb + 1 * PLANE_U32 * 4 + 16, arow_l + k0k + 8, abytes);
        cp16(sb + 2 * PLANE_U32 * 4,      brow_h + k0k, 16);
        cp16(sb + 2 * PLANE_U32 * 4 + 16, brow_h + k0k + 8, 16);
        cp16(sb + 3 * PLANE_U32 * 4,      brow_l + k0k, 16);
        cp16(sb + 3 * PLANE_U32 * 4 + 16, brow_l + k0k + 8, 16);
        cp_commit();
    };

    const int lane = tid & 31;
    const int wm = (tid >> 5) >> 2;  // 0..1
    const int wn = (tid >> 5) & 3;   // 0..3
    const int r = lane >> 2;
    const int c = lane & 3;

    float acc[4][4][4];
#pragma unroll
    for (int mt = 0; mt < 4; mt++)
#pragma unroll
        for (int nt = 0; nt < 4; nt++)
#pragma unroll
            for (int i = 0; i < 4; i++) acc[mt][nt][i] = 0.f;

    stage(0, 0);
    for (int kt = 0; kt < KT; kt++) {
        if (kt + 1 < KT) { stage((kt + 1) & 1, (kt + 1) * BK); cp_wait<1>(); }
        else             { cp_wait<0>(); }
        __syncthreads();
        const uint32_t* S = sm + (kt & 1) * STAGE_U32;
        const uint32_t* Ah = S;
        const uint32_t* Al = S + PLANE_U32;
        const uint32_t* Bh = S + 2 * PLANE_U32;
        const uint32_t* Bl = S + 3 * PLANE_U32;
#pragma unroll
        for (int ks = 0; ks < 2; ks++) {   // two k16 chunks per BK=32
            uint32_t bh[4][2], bl[4][2];
#pragma unroll
            for (int nt = 0; nt < 4; nt++) {
                const uint32_t* q = Bh + (wn * 32 + nt * 8 + r) * ROW_U32 + ks * 8 + c;
                bh[nt][0] = q[0]; bh[nt][1] = q[4];
                const uint32_t* ql = Bl + (wn * 32 + nt * 8 + r) * ROW_U32 + ks * 8 + c;
                bl[nt][0] = ql[0]; bl[nt][1] = ql[4];
            }
#pragma unroll
            for (int mt = 0; mt < 4; mt++) {
                int row = wm * 64 + mt * 16 + r;
                const uint32_t* p  = Ah + row * ROW_U32 + ks * 8 + c;
                uint32_t ah0 = p[0], ah1 = p[8 * ROW_U32], ah2 = p[4], ah3 = p[8 * ROW_U32 + 4];
                const uint32_t* pl = Al + row * ROW_U32 + ks * 8 + c;
                uint32_t al0 = pl[0], al1 = pl[8 * ROW_U32], al2 = pl[4], al3 = pl[8 * ROW_U32 + 4];
#pragma unroll
                for (int nt = 0; nt < 4; nt++) {
                    mma_bf16(acc[mt][nt], ah0, ah1, ah2, ah3, bh[nt][0], bh[nt][1]);
                    mma_bf16(acc[mt][nt], al0, al1, al2, al3, bh[nt][0], bh[nt][1]);
                    mma_bf16(acc[mt][nt], ah0, ah1, ah2, ah3, bl[nt][0], bl[nt][1]);
                }
            }
        }
        __syncthreads();
    }

    const float* bias = Bias + (size_t)e * NTOT;
#pragma unroll
    for (int mt = 0; mt < 4; mt++) {
        int row0 = m0 + wm * 64 + mt * 16 + r;
        int lrow = wm * 64 + mt * 16 + r;
#pragma unroll
        for (int nt = 0; nt < 4; nt++) {
            int col = n0 + wn * 32 + nt * 8 + 2 * c;
            float b0v = bias[col], b1v = bias[col + 1];
            float v0 = acc[mt][nt][0] + b0v, v1 = acc[mt][nt][1] + b1v;
            float v2 = acc[mt][nt][2] + b0v, v3 = acc[mt][nt][3] + b1v;
            if (RELU) {
                v0 = fmaxf(v0, 0.f); v1 = fmaxf(v1, 0.f);
                v2 = fmaxf(v2, 0.f); v3 = fmaxf(v3, 0.f);
                // write hidden as bf16 hi/lo planes
                size_t o0 = (size_t)row0 * NTOT + col;
                size_t o2 = o0 + (size_t)8 * NTOT;
                __nv_bfloat16 h;
                h = __float2bfloat16(v0); gh_hi[o0]     = h; gh_lo[o0]     = __float2bfloat16(v0 - __bfloat162float(h));
                h = __float2bfloat16(v1); gh_hi[o0 + 1] = h; gh_lo[o0 + 1] = __float2bfloat16(v1 - __bfloat162float(h));
                h = __float2bfloat16(v2); gh_hi[o2]     = h; gh_lo[o2]     = __float2bfloat16(v2 - __bfloat162float(h));
                h = __float2bfloat16(v3); gh_hi[o2 + 1] = h; gh_lo[o2 + 1] = __float2bfloat16(v3 - __bfloat162float(h));
            } else {
                float w0 = SCALE ? sW[lrow]     : 1.f;
                float w1 = SCALE ? sW[lrow + 8] : 1.f;
                float* o0 = g_ybuf + (size_t)row0 * NTOT + col;
                *(float2*)o0 = make_float2(v0 * w0, v1 * w0);
                *(float2*)(o0 + (size_t)8 * NTOT) = make_float2(v2 * w1, v3 * w1);
            }
        }
    }
}

// -------- deterministic combine --------
__global__ void combine_kernel(float* __restrict__ out) {
    int i = blockIdx.x * blockDim.x + threadIdx.x;
    if (i >= N_TOK * (D_IN / 4)) return;
    int t  = i >> 7;
    int dd = (i & 127) << 2;
    int s0 = g_tok_slot[t * 2 + 0];
    int s1 = g_tok_slot[t * 2 + 1];
    float4 a = *(const float4*)(g_ybuf + (size_t)s0 * D_IN + dd);
    float4 b = *(const float4*)(g_ybuf + (size_t)s1 * D_IN + dd);
    float4 r = make_float4(a.x + b.x, a.y + b.y, a.z + b.z, a.w + b.w);
    *(float4*)(out + (size_t)t * D_IN + dd) = r;
}

extern "C" void kernel_launch(void* const* d_in, const int* in_sizes, int n_in,
                              void* d_out, int out_size) {
    const float* x  = (const float*)d_in[0];
    const float* Wg = (const float*)d_in[1];
    const float* bg = (const float*)d_in[2];
    const float* W1 = (const float*)d_in[3];
    const float* b1 = (const float*)d_in[4];
    const float* W2 = (const float*)d_in[5];
    const float* b2 = (const float*)d_in[6];
    float* out = (float*)d_out;

    float* gates_out = nullptr;
    if (out_size >= N_TOK * D_IN + N_TOK * E_EXP)
        gates_out = out + (size_t)N_TOK * D_IN;

    cudaFuncSetAttribute(mma_gemm_kernel<D_IN, H_DIM, true, true, false>,
                         cudaFuncAttributeMaxDynamicSharedMemorySize, SMEM_BYTES);
    cudaFuncSetAttribute(mma_gemm_kernel<H_DIM, D_IN, false, false, true>,
                         cudaFuncAttributeMaxDynamicSharedMemorySize, SMEM_BYTES);

    init_kernel<<<(SLOTS + 255) / 256, 256>>>();
    gate_kernel<<<(N_TOK * 32 + 255) / 256, 256>>>(x, Wg, bg, gates_out);
    scan_kernel<<<1, 32>>>();
    scatter_kernel<<<(N_TOK * TOPK + 255) / 256, 256>>>();

    split_x_kernel<<<(N_TOK * D_IN + 255) / 256, 256>>>(x);
    {   // W1 [E][512][2048] -> planes [E][2048][512]
        __nv_bfloat16 *dhi, *dlo;
        cudaGetSymbolAddress((void**)&dhi, gW1t_hi);
        cudaGetSymbolAddress((void**)&dlo, gW1t_lo);
        dim3 g(H_DIM / 32, D_IN / 32, E_EXP);
        split_wt_kernel<<<g, 256>>>(W1, dhi, dlo, D_IN, H_DIM);
    }
    {   // W2 [E][2048][512] -> planes [E][512][2048]
        __nv_bfloat16 *dhi, *dlo;
        cudaGetSymbolAddress((void**)&dhi, gW2t_hi);
        cudaGetSymbolAddress((void**)&dlo, gW2t_lo);
        dim3 g(D_IN / 32, H_DIM / 32, E_EXP);
        split_wt_kernel<<<g, 256>>>(W2, dhi, dlo, H_DIM, D_IN);
    }

    __nv_bfloat16 *xhi, *xlo, *w1h, *w1l, *w2h, *w2l, *hhi, *hlo;
    cudaGetSymbolAddress((void**)&xhi, gx_hi);
    cudaGetSymbolAddress((void**)&xlo, gx_lo);
    cudaGetSymbolAddress((void**)&w1h, gW1t_hi);
    cudaGetSymbolAddress((void**)&w1l, gW1t_lo);
    cudaGetSymbolAddress((void**)&w2h, gW2t_hi);
    cudaGetSymbolAddress((void**)&w2l, gW2t_lo);
    cudaGetSymbolAddress((void**)&hhi, gh_hi);
    cudaGetSymbolAddress((void**)&hlo, gh_lo);

    dim3 g1(H_DIM / BN, SLOTS / BM);   // (16, 72)
    mma_gemm_kernel<D_IN, H_DIM, true, true, false>
        <<<g1, 256, SMEM_BYTES>>>(xhi, xlo, w1h, w1l, b1);

    dim3 g2(D_IN / BN, SLOTS / BM);    // (4, 72)
    mma_gemm_kernel<H_DIM, D_IN, false, false, true>
        <<<g2, 256, SMEM_BYTES>>>(hhi, hlo, w2h, w2l, b2);

    combine_kernel<<<(N_TOK * (D_IN / 4) + 255) / 256, 256>>>(out);
}

// round 6
// speedup vs baseline: 2.3263x; 1.1090x over previous
#include <cuda_runtime.h>
#include <cuda_bf16.h>
#include <math.h>
#include <stdint.h>

#define N_TOK 4096
#define D_IN  512
#define E_EXP 8
#define TOPK  2
#define H_DIM 2048

#define BM 128
#define BN 128
#define BK 32
#define SLOTS (N_TOK*TOPK + E_EXP*BM)   // 9216 padded slots

// smem: 4 planes (Ah, Al, Bh, Bl), each 128 rows x 32 bf16 (64B/row), XOR-swizzled
#define PLANE_BYTES 8192
#define OAH 0
#define OAL 8192
#define OBH 16384
#define OBL 24576
#define STAGE_BYTES 32768
#define SMEM_BYTES (2 * STAGE_BYTES)    // 65536

// -------- scratch (device globals; no allocation allowed) --------
__device__ int   g_counts[E_EXP];
__device__ int   g_off[E_EXP + 1];
__device__ int   g_wptr[E_EXP];
__device__ int   g_slot_tok[SLOTS];
__device__ float g_slot_w[SLOTS];
__device__ int   g_tok_slot[N_TOK * TOPK];
__device__ float g_topw[N_TOK * TOPK];
__device__ int   g_topi[N_TOK * TOPK];

__device__ __nv_bfloat16 gx_hi[(size_t)N_TOK * D_IN];
__device__ __nv_bfloat16 gx_lo[(size_t)N_TOK * D_IN];
__device__ __nv_bfloat16 gW1t_hi[(size_t)E_EXP * H_DIM * D_IN]; // [e][n][k]
__device__ __nv_bfloat16 gW1t_lo[(size_t)E_EXP * H_DIM * D_IN];
__device__ __nv_bfloat16 gW2t_hi[(size_t)E_EXP * D_IN * H_DIM]; // [e][n][k]
__device__ __nv_bfloat16 gW2t_lo[(size_t)E_EXP * D_IN * H_DIM];
__device__ __nv_bfloat16 gh_hi[(size_t)SLOTS * H_DIM];
__device__ __nv_bfloat16 gh_lo[(size_t)SLOTS * H_DIM];
__device__ float g_ybuf[(size_t)SLOTS * D_IN];

// -------- helpers --------
__device__ __forceinline__ void cp16(uint32_t dst, const void* src, int srcBytes) {
    asm volatile("cp.async.cg.shared.global [%0], [%1], 16, %2;"
                 :: "r"(dst), "l"(src), "r"(srcBytes) : "memory");
}
__device__ __forceinline__ void cp_commit() {
    asm volatile("cp.async.commit_group;" ::: "memory");
}
template<int N> __device__ __forceinline__ void cp_wait() {
    asm volatile("cp.async.wait_group %0;" :: "n"(N) : "memory");
}
__device__ __forceinline__ void ldsm4(uint32_t* r, uint32_t addr) {
    asm volatile("ldmatrix.sync.aligned.m8n8.x4.shared.b16 {%0,%1,%2,%3}, [%4];"
                 : "=r"(r[0]), "=r"(r[1]), "=r"(r[2]), "=r"(r[3]) : "r"(addr));
}
__device__ __forceinline__ void mma_bf16(float d[4],
                                         uint32_t a0, uint32_t a1, uint32_t a2, uint32_t a3,
                                         uint32_t b0, uint32_t b1) {
    asm volatile(
        "mma.sync.aligned.m16n8k16.row.col.f32.bf16.bf16.f32 "
        "{%0,%1,%2,%3},{%4,%5,%6,%7},{%8,%9},{%0,%1,%2,%3};"
        : "+f"(d[0]), "+f"(d[1]), "+f"(d[2]), "+f"(d[3])
        : "r"(a0), "r"(a1), "r"(a2), "r"(a3), "r"(b0), "r"(b1));
}
// swizzled byte offset of 16B chunk c (0..3) in row r of a plane
__device__ __forceinline__ uint32_t swz(int r, int c) {
    return (uint32_t)(r * 64 + ((c ^ ((r >> 1) & 3)) * 16));
}

// -------- init --------
__global__ void init_kernel() {
    int i = blockIdx.x * blockDim.x + threadIdx.x;
    if (i < E_EXP) g_counts[i] = 0;
    if (i < SLOTS) g_slot_tok[i] = -1;
}

// -------- gating: one warp per token --------
__global__ void gate_kernel(const float* __restrict__ x,
                            const float* __restrict__ Wg,
                            const float* __restrict__ bg,
                            float* __restrict__ gates_out) {
    int t    = (blockIdx.x * blockDim.x + threadIdx.x) >> 5;
    int lane = threadIdx.x & 31;
    if (t >= N_TOK) return;
    const float* xr = x + (size_t)t * D_IN;

    float acc[E_EXP];
#pragma unroll
    for (int e = 0; e < E_EXP; e++) acc[e] = 0.f;
    for (int d = lane; d < D_IN; d += 32) {
        float xv = xr[d];
        const float* wr = Wg + d * E_EXP;
#pragma unroll
        for (int e = 0; e < E_EXP; e++) acc[e] = fmaf(xv, wr[e], acc[e]);
    }
#pragma unroll
    for (int o = 16; o > 0; o >>= 1) {
#pragma unroll
        for (int e = 0; e < E_EXP; e++)
            acc[e] += __shfl_xor_sync(0xffffffffu, acc[e], o);
    }
    if (lane == 0) {
        float l[E_EXP], p[E_EXP];
        float m = -1e30f;
#pragma unroll
        for (int e = 0; e < E_EXP; e++) { l[e] = acc[e] + bg[e]; m = fmaxf(m, l[e]); }
        float s = 0.f;
#pragma unroll
        for (int e = 0; e < E_EXP; e++) { p[e] = __expf(l[e] - m); s += p[e]; }
        float inv = 1.f / s;
#pragma unroll
        for (int e = 0; e < E_EXP; e++) p[e] *= inv;
        if (gates_out) {
#pragma unroll
            for (int e = 0; e < E_EXP; e++) gates_out[t * E_EXP + e] = p[e];
        }
        int i1 = 0; float p1 = p[0];
#pragma unroll
        for (int e = 1; e < E_EXP; e++) if (p[e] > p1) { p1 = p[e]; i1 = e; }
        int i2 = -1; float p2 = -1.f;
#pragma unroll
        for (int e = 0; e < E_EXP; e++) if (e != i1 && p[e] > p2) { p2 = p[e]; i2 = e; }
        g_topw[t * 2 + 0] = p1;  g_topi[t * 2 + 0] = i1;
        g_topw[t * 2 + 1] = p2;  g_topi[t * 2 + 1] = i2;
        atomicAdd(&g_counts[i1], 1);
        atomicAdd(&g_counts[i2], 1);
    }
}

__global__ void scan_kernel() {
    if (threadIdx.x == 0 && blockIdx.x == 0) {
        int o = 0;
        for (int e = 0; e < E_EXP; e++) {
            g_off[e]  = o;
            g_wptr[e] = o;
            o += ((g_counts[e] + BM - 1) / BM) * BM;
        }
        g_off[E_EXP] = o;
    }
}

__global__ void scatter_kernel() {
    int i = blockIdx.x * blockDim.x + threadIdx.x;
    if (i >= N_TOK * TOPK) return;
    int e = g_topi[i];
    int pos = atomicAdd(&g_wptr[e], 1);
    g_slot_tok[pos] = i >> 1;
    g_slot_w[pos]   = g_topw[i];
    g_tok_slot[i]   = pos;
}

// -------- fp32 -> bf16 hi/lo split (x) --------
__global__ void split_x_kernel(const float* __restrict__ src) {
    int i = blockIdx.x * blockDim.x + threadIdx.x;
    if (i >= N_TOK * D_IN) return;
    float v = src[i];
    __nv_bfloat16 h = __float2bfloat16(v);
    gx_hi[i] = h;
    gx_lo[i] = __float2bfloat16(v - __bfloat162float(h));
}

// -------- fp32 [E][K][N] -> transposed bf16 hi/lo planes [E][N][K] --------
__global__ void split_wt_kernel(const float* __restrict__ src,
                                __nv_bfloat16* __restrict__ dhi,
                                __nv_bfloat16* __restrict__ dlo,
                                int K, int N) {
    __shared__ float t[32][33];
    int e = blockIdx.z;
    int k0 = blockIdx.y * 32, n0 = blockIdx.x * 32;
    const float* s = src + (size_t)e * K * N;
    int tx = threadIdx.x & 31, ty = threadIdx.x >> 5;
#pragma unroll
    for (int i = 0; i < 4; i++)
        t[ty + 8 * i][tx] = s[(size_t)(k0 + ty + 8 * i) * N + n0 + tx];
    __syncthreads();
    size_t ob = (size_t)e * K * N;
#pragma unroll
    for (int i = 0; i < 4; i++) {
        int n = n0 + ty + 8 * i, k = k0 + tx;
        float v = t[tx][ty + 8 * i];
        __nv_bfloat16 h = __float2bfloat16(v);
        dhi[ob + (size_t)n * K + k] = h;
        dlo[ob + (size_t)n * K + k] = __float2bfloat16(v - __bfloat162float(h));
    }
}

// -------- grouped bf16x3 tensor-core GEMM with ldmatrix --------
template<int KTOT, int NTOT, bool GATHER, bool RELU, bool SCALE>
__global__ void __launch_bounds__(256, 2)
mma_gemm_kernel(const __nv_bfloat16* __restrict__ Ahi,
                const __nv_bfloat16* __restrict__ Alo,
                const __nv_bfloat16* __restrict__ Bthi,
                const __nv_bfloat16* __restrict__ Btlo,
                const float* __restrict__ Bias)
{
    constexpr int KT = KTOT / BK;
    extern __shared__ char smem[];
    __shared__ int   sTok[BM];
    __shared__ float sW[BM];

    const int m0 = blockIdx.y * BM;
    const int n0 = blockIdx.x * BN;
    if (m0 >= g_off[E_EXP]) return;
    int e = 0;
#pragma unroll
    for (int i = 1; i < E_EXP; i++) if (m0 >= g_off[i]) e = i;

    const int tid = threadIdx.x;
    if (tid < BM) {
        if (GATHER) sTok[tid] = g_slot_tok[m0 + tid];
        if (SCALE)  sW[tid]   = g_slot_w[m0 + tid];
    }
    __syncthreads();

    const __nv_bfloat16* Wh = Bthi + (size_t)e * NTOT * KTOT;
    const __nv_bfloat16* Wl = Btlo + (size_t)e * NTOT * KTOT;

    // ---- staging: thread t -> row t>>1, chunks 2*(t&1)+{0,1} of each plane
    const int srow = tid >> 1;
    const int skoff = (tid & 1) * 16;   // bf16 offset in row

    const __nv_bfloat16 *arow_h, *arow_l;
    int abytes = 16;
    if (GATHER) {
        int tok = sTok[srow];
        if (tok >= 0) {
            arow_h = Ahi + (size_t)tok * KTOT + skoff;
            arow_l = Alo + (size_t)tok * KTOT + skoff;
        } else { arow_h = Ahi; arow_l = Alo; abytes = 0; }
    } else {
        arow_h = Ahi + (size_t)(m0 + srow) * KTOT + skoff;
        arow_l = Alo + (size_t)(m0 + srow) * KTOT + skoff;
    }
    const __nv_bfloat16* brow_h = Wh + (size_t)(n0 + srow) * KTOT + skoff;
    const __nv_bfloat16* brow_l = Wl + (size_t)(n0 + srow) * KTOT + skoff;

    const uint32_t sbase = (uint32_t)__cvta_generic_to_shared(smem);
    const uint32_t d0 = swz(srow, 2 * (tid & 1));
    const uint32_t d1 = swz(srow, 2 * (tid & 1) + 1);

    auto stage = [&](int buf, int k0) {
        uint32_t sb = sbase + buf * STAGE_BYTES;
        cp16(sb + OAH + d0, arow_h + k0,     abytes);
        cp16(sb + OAH + d1, arow_h + k0 + 8, abytes);
        cp16(sb + OAL + d0, arow_l + k0,     abytes);
        cp16(sb + OAL + d1, arow_l + k0 + 8, abytes);
        cp16(sb + OBH + d0, brow_h + k0,     16);
        cp16(sb + OBH + d1, brow_h + k0 + 8, 16);
        cp16(sb + OBL + d0, brow_l + k0,     16);
        cp16(sb + OBL + d1, brow_l + k0 + 8, 16);
        cp_commit();
    };

    // ---- fragment addressing (ldmatrix)
    const int lane = tid & 31;
    const int wm = (tid >> 5) >> 2;  // 0..1
    const int wn = (tid >> 5) & 3;   // 0..3
    const int g  = lane >> 3;        // ldmatrix address group
    const int lr = lane & 7;

    // A: row = wm*64 + mt*16 + lr + (g&1)*8 ; chunk = ks*2 + (g>>1)
    const int arow0 = wm * 64 + lr + (g & 1) * 8;
    const uint32_t aswz = ((uint32_t)(arow0 >> 1) & 3);   // invariant under +mt*16
    uint32_t aoff[2];
#pragma unroll
    for (int ks = 0; ks < 2; ks++)
        aoff[ks] = (uint32_t)(arow0 * 64) + (((uint32_t)(ks * 2 + (g >> 1)) ^ aswz) * 16);

    // B: row = wn*32 + np*16 + lr + ((g>>1)&1)*8 ; chunk = ks*2 + (g&1)
    const int brow0 = wn * 32 + lr + ((g >> 1) & 1) * 8;
    const uint32_t bswz = ((uint32_t)(brow0 >> 1) & 3);   // invariant under +np*16
    uint32_t boff[2];
#pragma unroll
    for (int ks = 0; ks < 2; ks++)
        boff[ks] = (uint32_t)(brow0 * 64) + (((uint32_t)(ks * 2 + (g & 1)) ^ bswz) * 16);

    float acc[4][4][4];
#pragma unroll
    for (int mt = 0; mt < 4; mt++)
#pragma unroll
        for (int nt = 0; nt < 4; nt++)
#pragma unroll
            for (int i = 0; i < 4; i++) acc[mt][nt][i] = 0.f;

    stage(0, 0);
    for (int kt = 0; kt < KT; kt++) {
        if (kt + 1 < KT) { stage((kt + 1) & 1, (kt + 1) * BK); cp_wait<1>(); }
        else             { cp_wait<0>(); }
        __syncthreads();
        const uint32_t sb = sbase + (kt & 1) * STAGE_BYTES;
#pragma unroll
        for (int ks = 0; ks < 2; ks++) {
            uint32_t bh[8], bl[8];
#pragma unroll
            for (int np = 0; np < 2; np++) {
                ldsm4(&bh[np * 4], sb + OBH + boff[ks] + np * 1024);
                ldsm4(&bl[np * 4], sb + OBL + boff[ks] + np * 1024);
            }
#pragma unroll
            for (int mt = 0; mt < 4; mt++) {
                uint32_t ah[4], al[4];
                ldsm4(ah, sb + OAH + aoff[ks] + mt * 1024);
                ldsm4(al, sb + OAL + aoff[ks] + mt * 1024);
#pragma unroll
                for (int nt = 0; nt < 4; nt++) {
                    int i0 = (nt >> 1) * 4 + (nt & 1) * 2;
                    uint32_t b0h = bh[i0], b1h = bh[i0 + 1];
                    uint32_t b0l = bl[i0], b1l = bl[i0 + 1];
                    mma_bf16(acc[mt][nt], ah[0], ah[1], ah[2], ah[3], b0h, b1h);
                    mma_bf16(acc[mt][nt], al[0], al[1], al[2], al[3], b0h, b1h);
                    mma_bf16(acc[mt][nt], ah[0], ah[1], ah[2], ah[3], b0l, b1l);
                }
            }
        }
        __syncthreads();
    }

    const int r = lane >> 2;
    const int c = lane & 3;
    const float* bias = Bias + (size_t)e * NTOT;
#pragma unroll
    for (int mt = 0; mt < 4; mt++) {
        int row0 = m0 + wm * 64 + mt * 16 + r;
        int lrow = wm * 64 + mt * 16 + r;
#pragma unroll
        for (int nt = 0; nt < 4; nt++) {
            int col = n0 + wn * 32 + nt * 8 + 2 * c;
            float b0v = bias[col], b1v = bias[col + 1];
            float v0 = acc[mt][nt][0] + b0v, v1 = acc[mt][nt][1] + b1v;
            float v2 = acc[mt][nt][2] + b0v, v3 = acc[mt][nt][3] + b1v;
            if (RELU) {
                v0 = fmaxf(v0, 0.f); v1 = fmaxf(v1, 0.f);
                v2 = fmaxf(v2, 0.f); v3 = fmaxf(v3, 0.f);
                size_t o0 = (size_t)row0 * NTOT + col;
                size_t o2 = o0 + (size_t)8 * NTOT;
                __nv_bfloat16 h;
                h = __float2bfloat16(v0); gh_hi[o0]     = h; gh_lo[o0]     = __float2bfloat16(v0 - __bfloat162float(h));
                h = __float2bfloat16(v1); gh_hi[o0 + 1] = h; gh_lo[o0 + 1] = __float2bfloat16(v1 - __bfloat162float(h));
                h = __float2bfloat16(v2); gh_hi[o2]     = h; gh_lo[o2]     = __float2bfloat16(v2 - __bfloat162float(h));
                h = __float2bfloat16(v3); gh_hi[o2 + 1] = h; gh_lo[o2 + 1] = __float2bfloat16(v3 - __bfloat162float(h));
            } else {
                float w0 = SCALE ? sW[lrow]     : 1.f;
                float w1 = SCALE ? sW[lrow + 8] : 1.f;
                float* o0 = g_ybuf + (size_t)row0 * NTOT + col;
                *(float2*)o0 = make_float2(v0 * w0, v1 * w0);
                *(float2*)(o0 + (size_t)8 * NTOT) = make_float2(v2 * w1, v3 * w1);
            }
        }
    }
}

// -------- deterministic combine --------
__global__ void combine_kernel(float* __restrict__ out) {
    int i = blockIdx.x * blockDim.x + threadIdx.x;
    if (i >= N_TOK * (D_IN / 4)) return;
    int t  = i >> 7;
    int dd = (i & 127) << 2;
    int s0 = g_tok_slot[t * 2 + 0];
    int s1 = g_tok_slot[t * 2 + 1];
    float4 a = *(const float4*)(g_ybuf + (size_t)s0 * D_IN + dd);
    float4 b = *(const float4*)(g_ybuf + (size_t)s1 * D_IN + dd);
    float4 r = make_float4(a.x + b.x, a.y + b.y, a.z + b.z, a.w + b.w);
    *(float4*)(out + (size_t)t * D_IN + dd) = r;
}

extern "C" void kernel_launch(void* const* d_in, const int* in_sizes, int n_in,
                              void* d_out, int out_size) {
    const float* x  = (const float*)d_in[0];
    const float* Wg = (const float*)d_in[1];
    const float* bg = (const float*)d_in[2];
    const float* W1 = (const float*)d_in[3];
    const float* b1 = (const float*)d_in[4];
    const float* W2 = (const float*)d_in[5];
    const float* b2 = (const float*)d_in[6];
    float* out = (float*)d_out;

    float* gates_out = nullptr;
    if (out_size >= N_TOK * D_IN + N_TOK * E_EXP)
        gates_out = out + (size_t)N_TOK * D_IN;

    cudaFuncSetAttribute(mma_gemm_kernel<D_IN, H_DIM, true, true, false>,
                         cudaFuncAttributeMaxDynamicSharedMemorySize, SMEM_BYTES);
    cudaFuncSetAttribute(mma_gemm_kernel<H_DIM, D_IN, false, false, true>,
                         cudaFuncAttributeMaxDynamicSharedMemorySize, SMEM_BYTES);

    init_kernel<<<(SLOTS + 255) / 256, 256>>>();
    gate_kernel<<<(N_TOK * 32 + 255) / 256, 256>>>(x, Wg, bg, gates_out);
    scan_kernel<<<1, 32>>>();
    scatter_kernel<<<(N_TOK * TOPK + 255) / 256, 256>>>();

    split_x_kernel<<<(N_TOK * D_IN + 255) / 256, 256>>>(x);
    {
        __nv_bfloat16 *dhi, *dlo;
        cudaGetSymbolAddress((void**)&dhi, gW1t_hi);
        cudaGetSymbolAddress((void**)&dlo, gW1t_lo);
        dim3 g(H_DIM / 32, D_IN / 32, E_EXP);
        split_wt_kernel<<<g, 256>>>(W1, dhi, dlo, D_IN, H_DIM);
    }
    {
        __nv_bfloat16 *dhi, *dlo;
        cudaGetSymbolAddress((void**)&dhi, gW2t_hi);
        cudaGetSymbolAddress((void**)&dlo, gW2t_lo);
        dim3 g(D_IN / 32, H_DIM / 32, E_EXP);
        split_wt_kernel<<<g, 256>>>(W2, dhi, dlo, H_DIM, D_IN);
    }

    __nv_bfloat16 *xhi, *xlo, *w1h, *w1l, *w2h, *w2l, *hhi, *hlo;
    cudaGetSymbolAddress((void**)&xhi, gx_hi);
    cudaGetSymbolAddress((void**)&xlo, gx_lo);
    cudaGetSymbolAddress((void**)&w1h, gW1t_hi);
    cudaGetSymbolAddress((void**)&w1l, gW1t_lo);
    cudaGetSymbolAddress((void**)&w2h, gW2t_hi);
    cudaGetSymbolAddress((void**)&w2l, gW2t_lo);
    cudaGetSymbolAddress((void**)&hhi, gh_hi);
    cudaGetSymbolAddress((void**)&hlo, gh_lo);

    dim3 g1(H_DIM / BN, SLOTS / BM);   // (16, 72)
    mma_gemm_kernel<D_IN, H_DIM, true, true, false>
        <<<g1, 256, SMEM_BYTES>>>(xhi, xlo, w1h, w1l, b1);

    dim3 g2(D_IN / BN, SLOTS / BM);    // (4, 72)
    mma_gemm_kernel<H_DIM, D_IN, false, false, true>
        <<<g2, 256, SMEM_BYTES>>>(hhi, hlo, w2h, w2l, b2);

    combine_kernel<<<(N_TOK * (D_IN / 4) + 255) / 256, 256>>>(out);
}

// round 7
// speedup vs baseline: 2.3950x; 1.0295x over previous
#include <cuda_runtime.h>
#include <cuda_bf16.h>
#include <math.h>
#include <stdint.h>

#define N_TOK 4096
#define D_IN  512
#define E_EXP 8
#define TOPK  2
#define H_DIM 2048

#define BM 128
#define BN 128
#define BK 32
#define SLOTS (N_TOK*TOPK + E_EXP*BM)   // 9216 padded slots

// smem: 4 planes (Ah, Al, Bh, Bl), each 128 rows x 32 bf16 (64B/row), XOR-swizzled
#define PLANE_BYTES 8192
#define OAH 0
#define OAL 8192
#define OBH 16384
#define OBL 24576
#define STAGE_BYTES 32768
#define NSTAGE 3
#define SMEM_BYTES (NSTAGE * STAGE_BYTES)   // 98304

// -------- scratch (device globals; no allocation allowed) --------
__device__ int   g_counts[E_EXP];
__device__ int   g_cnt2[E_EXP];
__device__ int   g_off[E_EXP + 1];
__device__ int   g_slot_tok[SLOTS];
__device__ float g_slot_w[SLOTS];
__device__ int   g_tok_slot[N_TOK * TOPK];
__device__ float g_topw[N_TOK * TOPK];
__device__ int   g_topi[N_TOK * TOPK];

__device__ __nv_bfloat16 gx_hi[(size_t)N_TOK * D_IN];
__device__ __nv_bfloat16 gx_lo[(size_t)N_TOK * D_IN];
__device__ __nv_bfloat16 gW1t_hi[(size_t)E_EXP * H_DIM * D_IN]; // [e][n][k]
__device__ __nv_bfloat16 gW1t_lo[(size_t)E_EXP * H_DIM * D_IN];
__device__ __nv_bfloat16 gW2t_hi[(size_t)E_EXP * D_IN * H_DIM]; // [e][n][k]
__device__ __nv_bfloat16 gW2t_lo[(size_t)E_EXP * D_IN * H_DIM];
__device__ __nv_bfloat16 gh_hi[(size_t)SLOTS * H_DIM];
__device__ __nv_bfloat16 gh_lo[(size_t)SLOTS * H_DIM];
__device__ float g_ybuf[(size_t)SLOTS * D_IN];

// -------- helpers --------
__device__ __forceinline__ void cp16(uint32_t dst, const void* src, int srcBytes) {
    asm volatile("cp.async.cg.shared.global [%0], [%1], 16, %2;"
                 :: "r"(dst), "l"(src), "r"(srcBytes) : "memory");
}
__device__ __forceinline__ void cp_commit() {
    asm volatile("cp.async.commit_group;" ::: "memory");
}
template<int N> __device__ __forceinline__ void cp_wait() {
    asm volatile("cp.async.wait_group %0;" :: "n"(N) : "memory");
}
__device__ __forceinline__ void ldsm4(uint32_t* r, uint32_t addr) {
    asm volatile("ldmatrix.sync.aligned.m8n8.x4.shared.b16 {%0,%1,%2,%3}, [%4];"
                 : "=r"(r[0]), "=r"(r[1]), "=r"(r[2]), "=r"(r[3]) : "r"(addr));
}
__device__ __forceinline__ void mma_bf16(float d[4],
                                         uint32_t a0, uint32_t a1, uint32_t a2, uint32_t a3,
                                         uint32_t b0, uint32_t b1) {
    asm volatile(
        "mma.sync.aligned.m16n8k16.row.col.f32.bf16.bf16.f32 "
        "{%0,%1,%2,%3},{%4,%5,%6,%7},{%8,%9},{%0,%1,%2,%3};"
        : "+f"(d[0]), "+f"(d[1]), "+f"(d[2]), "+f"(d[3])
        : "r"(a0), "r"(a1), "r"(a2), "r"(a3), "r"(b0), "r"(b1));
}
// swizzled byte offset of 16B chunk c (0..3) in row r of a plane
__device__ __forceinline__ uint32_t swz(int r, int c) {
    return (uint32_t)(r * 64 + ((c ^ ((r >> 1) & 3)) * 16));
}

// -------- gating: one warp per token --------
__global__ void gate_kernel(const float* __restrict__ x,
                            const float* __restrict__ Wg,
                            const float* __restrict__ bg,
                            float* __restrict__ gates_out) {
    int t    = (blockIdx.x * blockDim.x + threadIdx.x) >> 5;
    int lane = threadIdx.x & 31;
    if (t >= N_TOK) return;
    const float* xr = x + (size_t)t * D_IN;

    float acc[E_EXP];
#pragma unroll
    for (int e = 0; e < E_EXP; e++) acc[e] = 0.f;
    for (int d = lane; d < D_IN; d += 32) {
        float xv = xr[d];
        const float* wr = Wg + d * E_EXP;
#pragma unroll
        for (int e = 0; e < E_EXP; e++) acc[e] = fmaf(xv, wr[e], acc[e]);
    }
#pragma unroll
    for (int o = 16; o > 0; o >>= 1) {
#pragma unroll
        for (int e = 0; e < E_EXP; e++)
            acc[e] += __shfl_xor_sync(0xffffffffu, acc[e], o);
    }
    if (lane == 0) {
        float l[E_EXP], p[E_EXP];
        float m = -1e30f;
#pragma unroll
        for (int e = 0; e < E_EXP; e++) { l[e] = acc[e] + bg[e]; m = fmaxf(m, l[e]); }
        float s = 0.f;
#pragma unroll
        for (int e = 0; e < E_EXP; e++) { p[e] = __expf(l[e] - m); s += p[e]; }
        float inv = 1.f / s;
#pragma unroll
        for (int e = 0; e < E_EXP; e++) p[e] *= inv;
        if (gates_out) {
#pragma unroll
            for (int e = 0; e < E_EXP; e++) gates_out[t * E_EXP + e] = p[e];
        }
        int i1 = 0; float p1 = p[0];
#pragma unroll
        for (int e = 1; e < E_EXP; e++) if (p[e] > p1) { p1 = p[e]; i1 = e; }
        int i2 = -1; float p2 = -1.f;
#pragma unroll
        for (int e = 0; e < E_EXP; e++) if (e != i1 && p[e] > p2) { p2 = p[e]; i2 = e; }
        g_topw[t * 2 + 0] = p1;  g_topi[t * 2 + 0] = i1;
        g_topw[t * 2 + 1] = p2;  g_topi[t * 2 + 1] = i2;
        atomicAdd(&g_counts[i1], 1);
        atomicAdd(&g_counts[i2], 1);
    }
}

// -------- scatter (scan folded in; every block recomputes 8-entry scan) --------
__global__ void scatter_kernel() {
    __shared__ int soff[E_EXP + 1];
    if (threadIdx.x == 0) {
        int o = 0;
#pragma unroll
        for (int e = 0; e < E_EXP; e++) {
            soff[e] = o;
            o += ((g_counts[e] + BM - 1) / BM) * BM;
        }
        soff[E_EXP] = o;
        if (blockIdx.x == 0) {
#pragma unroll
            for (int e = 0; e <= E_EXP; e++) g_off[e] = soff[e];
        }
    }
    __syncthreads();
    int i = blockIdx.x * blockDim.x + threadIdx.x;
    if (i >= N_TOK * TOPK) return;
    int e = g_topi[i];
    int pos = soff[e] + atomicAdd(&g_cnt2[e], 1);
    g_slot_tok[pos] = i >> 1;
    g_slot_w[pos]   = g_topw[i];
    g_tok_slot[i]   = pos;
}

// -------- fp32 -> bf16 hi/lo split (x) --------
__global__ void split_x_kernel(const float* __restrict__ src) {
    int i = blockIdx.x * blockDim.x + threadIdx.x;
    if (i >= N_TOK * D_IN) return;
    float v = src[i];
    __nv_bfloat16 h = __float2bfloat16(v);
    gx_hi[i] = h;
    gx_lo[i] = __float2bfloat16(v - __bfloat162float(h));
}

// -------- fp32 [E][K][N] -> transposed bf16 hi/lo planes [E][N][K] --------
// INIT: also zero routing state (fold init kernel in; runs before gate).
template<bool INIT>
__global__ void split_wt_kernel(const float* __restrict__ src,
                                __nv_bfloat16* __restrict__ dhi,
                                __nv_bfloat16* __restrict__ dlo,
                                int K, int N) {
    if (INIT && blockIdx.z == 0 && blockIdx.y == 0) {
        int idx = blockIdx.x * blockDim.x + threadIdx.x;
        if (idx < SLOTS) g_slot_tok[idx] = -1;
        if (idx < E_EXP) { g_counts[idx] = 0; g_cnt2[idx] = 0; }
    }
    __shared__ float t[32][33];
    int e = blockIdx.z;
    int k0 = blockIdx.y * 32, n0 = blockIdx.x * 32;
    const float* s = src + (size_t)e * K * N;
    int tx = threadIdx.x & 31, ty = threadIdx.x >> 5;
#pragma unroll
    for (int i = 0; i < 4; i++)
        t[ty + 8 * i][tx] = s[(size_t)(k0 + ty + 8 * i) * N + n0 + tx];
    __syncthreads();
    size_t ob = (size_t)e * K * N;
#pragma unroll
    for (int i = 0; i < 4; i++) {
        int n = n0 + ty + 8 * i, k = k0 + tx;
        float v = t[tx][ty + 8 * i];
        __nv_bfloat16 h = __float2bfloat16(v);
        dhi[ob + (size_t)n * K + k] = h;
        dlo[ob + (size_t)n * K + k] = __float2bfloat16(v - __bfloat162float(h));
    }
}

// -------- grouped bf16x3 tensor-core GEMM, 3-stage pipeline --------
template<int KTOT, int NTOT, bool GATHER, bool RELU, bool SCALE>
__global__ void __launch_bounds__(256, 2)
mma_gemm_kernel(const __nv_bfloat16* __restrict__ Ahi,
                const __nv_bfloat16* __restrict__ Alo,
                const __nv_bfloat16* __restrict__ Bthi,
                const __nv_bfloat16* __restrict__ Btlo,
                const float* __restrict__ Bias)
{
    constexpr int KT = KTOT / BK;
    extern __shared__ char smem[];
    __shared__ int   sTok[BM];
    __shared__ float sW[BM];

    const int m0 = blockIdx.y * BM;
    const int n0 = blockIdx.x * BN;
    if (m0 >= g_off[E_EXP]) return;
    int e = 0;
#pragma unroll
    for (int i = 1; i < E_EXP; i++) if (m0 >= g_off[i]) e = i;

    const int tid = threadIdx.x;
    if (tid < BM) {
        if (GATHER) sTok[tid] = g_slot_tok[m0 + tid];
        if (SCALE)  sW[tid]   = g_slot_w[m0 + tid];
    }
    __syncthreads();

    const __nv_bfloat16* Wh = Bthi + (size_t)e * NTOT * KTOT;
    const __nv_bfloat16* Wl = Btlo + (size_t)e * NTOT * KTOT;

    // ---- staging: thread t -> row t>>1, chunks 2*(t&1)+{0,1} of each plane
    const int srow = tid >> 1;
    const int skoff = (tid & 1) * 16;   // bf16 offset in row

    const __nv_bfloat16 *arow_h, *arow_l;
    int abytes = 16;
    if (GATHER) {
        int tok = sTok[srow];
        if (tok >= 0) {
            arow_h = Ahi + (size_t)tok * KTOT + skoff;
            arow_l = Alo + (size_t)tok * KTOT + skoff;
        } else { arow_h = Ahi; arow_l = Alo; abytes = 0; }
    } else {
        arow_h = Ahi + (size_t)(m0 + srow) * KTOT + skoff;
        arow_l = Alo + (size_t)(m0 + srow) * KTOT + skoff;
    }
    const __nv_bfloat16* brow_h = Wh + (size_t)(n0 + srow) * KTOT + skoff;
    const __nv_bfloat16* brow_l = Wl + (size_t)(n0 + srow) * KTOT + skoff;

    const uint32_t sbase = (uint32_t)__cvta_generic_to_shared(smem);
    const uint32_t d0 = swz(srow, 2 * (tid & 1));
    const uint32_t d1 = swz(srow, 2 * (tid & 1) + 1);

    auto stage = [&](int buf, int k0) {
        uint32_t sb = sbase + buf * STAGE_BYTES;
        cp16(sb + OAH + d0, arow_h + k0,     abytes);
        cp16(sb + OAH + d1, arow_h + k0 + 8, abytes);
        cp16(sb + OAL + d0, arow_l + k0,     abytes);
        cp16(sb + OAL + d1, arow_l + k0 + 8, abytes);
        cp16(sb + OBH + d0, brow_h + k0,     16);
        cp16(sb + OBH + d1, brow_h + k0 + 8, 16);
        cp16(sb + OBL + d0, brow_l + k0,     16);
        cp16(sb + OBL + d1, brow_l + k0 + 8, 16);
        cp_commit();
    };

    // ---- fragment addressing (ldmatrix)
    const int lane = tid & 31;
    const int wm = (tid >> 5) >> 2;  // 0..1
    const int wn = (tid >> 5) & 3;   // 0..3
    const int g  = lane >> 3;        // ldmatrix address group
    const int lr = lane & 7;

    const int arow0 = wm * 64 + lr + (g & 1) * 8;
    const uint32_t aswz = ((uint32_t)(arow0 >> 1) & 3);
    uint32_t aoff[2];
#pragma unroll
    for (int ks = 0; ks < 2; ks++)
        aoff[ks] = (uint32_t)(arow0 * 64) + (((uint32_t)(ks * 2 + (g >> 1)) ^ aswz) * 16);

    const int brow0 = wn * 32 + lr + ((g >> 1) & 1) * 8;
    const uint32_t bswz = ((uint32_t)(brow0 >> 1) & 3);
    uint32_t boff[2];
#pragma unroll
    for (int ks = 0; ks < 2; ks++)
        boff[ks] = (uint32_t)(brow0 * 64) + (((uint32_t)(ks * 2 + (g & 1)) ^ bswz) * 16);

    float acc[4][4][4];
#pragma unroll
    for (int mt = 0; mt < 4; mt++)
#pragma unroll
        for (int nt = 0; nt < 4; nt++)
#pragma unroll
            for (int i = 0; i < 4; i++) acc[mt][nt][i] = 0.f;

    // 3-stage pipeline: one __syncthreads per iteration
    stage(0, 0);
    stage(1, BK);
    int buf = 0;
    for (int kt = 0; kt < KT; kt++) {
        if (kt < KT - 1) cp_wait<1>(); else cp_wait<0>();
        __syncthreads();   // buf `buf` ready for all; all warps done reading buf (kt+2)%3
        if (kt + 2 < KT) {
            int nb = buf + 2; if (nb >= NSTAGE) nb -= NSTAGE;
            stage(nb, (kt + 2) * BK);
        }
        const uint32_t sb = sbase + buf * STAGE_BYTES;
#pragma unroll
        for (int ks = 0; ks < 2; ks++) {
            uint32_t bh[8], bl[8];
#pragma unroll
            for (int np = 0; np < 2; np++) {
                ldsm4(&bh[np * 4], sb + OBH + boff[ks] + np * 1024);
                ldsm4(&bl[np * 4], sb + OBL + boff[ks] + np * 1024);
            }
#pragma unroll
            for (int mt = 0; mt < 4; mt++) {
                uint32_t ah[4], al[4];
                ldsm4(ah, sb + OAH + aoff[ks] + mt * 1024);
                ldsm4(al, sb + OAL + aoff[ks] + mt * 1024);
#pragma unroll
                for (int nt = 0; nt < 4; nt++) {
                    int i0 = (nt >> 1) * 4 + (nt & 1) * 2;
                    uint32_t b0h = bh[i0], b1h = bh[i0 + 1];
                    uint32_t b0l = bl[i0], b1l = bl[i0 + 1];
                    mma_bf16(acc[mt][nt], ah[0], ah[1], ah[2], ah[3], b0h, b1h);
                    mma_bf16(acc[mt][nt], al[0], al[1], al[2], al[3], b0h, b1h);
                    mma_bf16(acc[mt][nt], ah[0], ah[1], ah[2], ah[3], b0l, b1l);
                }
            }
        }
        buf++; if (buf >= NSTAGE) buf = 0;
    }

    const int r = lane >> 2;
    const int c = lane & 3;
    const float* bias = Bias + (size_t)e * NTOT;
#pragma unroll
    for (int mt = 0; mt < 4; mt++) {
        int row0 = m0 + wm * 64 + mt * 16 + r;
        int lrow = wm * 64 + mt * 16 + r;
#pragma unroll
        for (int nt = 0; nt < 4; nt++) {
            int col = n0 + wn * 32 + nt * 8 + 2 * c;
            float b0v = bias[col], b1v = bias[col + 1];
            float v0 = acc[mt][nt][0] + b0v, v1 = acc[mt][nt][1] + b1v;
            float v2 = acc[mt][nt][2] + b0v, v3 = acc[mt][nt][3] + b1v;
            if (RELU) {
                v0 = fmaxf(v0, 0.f); v1 = fmaxf(v1, 0.f);
                v2 = fmaxf(v2, 0.f); v3 = fmaxf(v3, 0.f);
                size_t o0 = (size_t)row0 * NTOT + col;
                size_t o2 = o0 + (size_t)8 * NTOT;
                __nv_bfloat16 h;
                h = __float2bfloat16(v0); gh_hi[o0]     = h; gh_lo[o0]     = __float2bfloat16(v0 - __bfloat162float(h));
                h = __float2bfloat16(v1); gh_hi[o0 + 1] = h; gh_lo[o0 + 1] = __float2bfloat16(v1 - __bfloat162float(h));
                h = __float2bfloat16(v2); gh_hi[o2]     = h; gh_lo[o2]     = __float2bfloat16(v2 - __bfloat162float(h));
                h = __float2bfloat16(v3); gh_hi[o2 + 1] = h; gh_lo[o2 + 1] = __float2bfloat16(v3 - __bfloat162float(h));
            } else {
                float w0 = SCALE ? sW[lrow]     : 1.f;
                float w1 = SCALE ? sW[lrow + 8] : 1.f;
                float* o0 = g_ybuf + (size_t)row0 * NTOT + col;
                *(float2*)o0 = make_float2(v0 * w0, v1 * w0);
                *(float2*)(o0 + (size_t)8 * NTOT) = make_float2(v2 * w1, v3 * w1);
            }
        }
    }
}

// -------- deterministic combine --------
__global__ void combine_kernel(float* __restrict__ out) {
    int i = blockIdx.x * blockDim.x + threadIdx.x;
    if (i >= N_TOK * (D_IN / 4)) return;
    int t  = i >> 7;
    int dd = (i & 127) << 2;
    int s0 = g_tok_slot[t * 2 + 0];
    int s1 = g_tok_slot[t * 2 + 1];
    float4 a = *(const float4*)(g_ybuf + (size_t)s0 * D_IN + dd);
    float4 b = *(const float4*)(g_ybuf + (size_t)s1 * D_IN + dd);
    float4 r = make_float4(a.x + b.x, a.y + b.y, a.z + b.z, a.w + b.w);
    *(float4*)(out + (size_t)t * D_IN + dd) = r;
}

extern "C" void kernel_launch(void* const* d_in, const int* in_sizes, int n_in,
                              void* d_out, int out_size) {
    const float* x  = (const float*)d_in[0];
    const float* Wg = (const float*)d_in[1];
    const float* bg = (const float*)d_in[2];
    const float* W1 = (const float*)d_in[3];
    const float* b1 = (const float*)d_in[4];
    const float* W2 = (const float*)d_in[5];
    const float* b2 = (const float*)d_in[6];
    float* out = (float*)d_out;

    float* gates_out = nullptr;
    if (out_size >= N_TOK * D_IN + N_TOK * E_EXP)
        gates_out = out + (size_t)N_TOK * D_IN;

    cudaFuncSetAttribute(mma_gemm_kernel<D_IN, H_DIM, true, true, false>,
                         cudaFuncAttributeMaxDynamicSharedMemorySize, SMEM_BYTES);
    cudaFuncSetAttribute(mma_gemm_kernel<H_DIM, D_IN, false, false, true>,
                         cudaFuncAttributeMaxDynamicSharedMemorySize, SMEM_BYTES);

    __nv_bfloat16 *xhi, *xlo, *w1h, *w1l, *w2h, *w2l, *hhi, *hlo;
    cudaGetSymbolAddress((void**)&xhi, gx_hi);
    cudaGetSymbolAddress((void**)&xlo, gx_lo);
    cudaGetSymbolAddress((void**)&w1h, gW1t_hi);
    cudaGetSymbolAddress((void**)&w1l, gW1t_lo);
    cudaGetSymbolAddress((void**)&w2h, gW2t_hi);
    cudaGetSymbolAddress((void**)&w2l, gW2t_lo);
    cudaGetSymbolAddress((void**)&hhi, gh_hi);
    cudaGetSymbolAddress((void**)&hlo, gh_lo);

    // 1: W1 split + routing-state init
    {
        dim3 g(H_DIM / 32, D_IN / 32, E_EXP);
        split_wt_kernel<true><<<g, 256>>>(W1, w1h, w1l, D_IN, H_DIM);
    }
    // 2: W2 split
    {
        dim3 g(D_IN / 32, H_DIM / 32, E_EXP);
        split_wt_kernel<false><<<g, 256>>>(W2, w2h, w2l, H_DIM, D_IN);
    }
    // 3: x split
    split_x_kernel<<<(N_TOK * D_IN + 255) / 256, 256>>>(x);
    // 4: gate
    gate_kernel<<<(N_TOK * 32 + 255) / 256, 256>>>(x, Wg, bg, gates_out);
    // 5: scatter (scan folded in)
    scatter_kernel<<<(N_TOK * TOPK + 255) / 256, 256>>>();
    // 6: GEMM1 (profiled slot)
    dim3 g1(H_DIM / BN, SLOTS / BM);   // (16, 72)
    mma_gemm_kernel<D_IN, H_DIM, true, true, false>
        <<<g1, 256, SMEM_BYTES>>>(xhi, xlo, w1h, w1l, b1);
    // 7: GEMM2
    dim3 g2(D_IN / BN, SLOTS / BM);    // (4, 72)
    mma_gemm_kernel<H_DIM, D_IN, false, false, true>
        <<<g2, 256, SMEM_BYTES>>>(hhi, hlo, w2h, w2l, b2);
    // 8: combine
    combine_kernel<<<(N_TOK * (D_IN / 4) + 255) / 256, 256>>>(out);
}